// round 14
// baseline (speedup 1.0000x reference)
#include <cuda_runtime.h>
#include <cuda_bf16.h>
#include <math_constants.h>
#include <cstdint>

// ---------------- problem constants ----------------
#define N_NODES 20000
#define N_EDGES 320000
#define F_IN    256
#define HIDC    64
#define HEADS   8
#define NCLS    64
#define HC1     (HEADS*HIDC)      // 512
#define NEG_SLOPE 0.2f
#define SM_EPS  1e-16f

typedef unsigned long long u64;

// ---------------- scratch (static device globals; no allocs) ----------------
__device__ float g_xlr1[(size_t)N_NODES * 1024];   // [N][xl1(512) | xr1(512)]
__device__ float g_xlr2[(size_t)N_NODES * 128];    // [N][xl2(64) | xr2(64)]
__device__ int   g_deg[N_NODES];
__device__ int   g_off[N_NODES + 1];
__device__ int   g_cur[N_NODES];
__device__ int   g_esrc[N_EDGES];                  // CSR-ordered source node ids

// bf16 split operands
__device__ __nv_bfloat16 g_xhi[(size_t)N_NODES * F_IN];
__device__ __nv_bfloat16 g_xlo[(size_t)N_NODES * F_IN];
__device__ __nv_bfloat16 g_hhi[(size_t)N_NODES * HC1];   // written by node1 epilogue
__device__ __nv_bfloat16 g_hlo[(size_t)N_NODES * HC1];
__device__ __nv_bfloat16 g_wt1hi[1024 * 256];   // [Ntot=1024][K=256] (W^T, K-contig)
__device__ __nv_bfloat16 g_wt1lo[1024 * 256];
__device__ __nv_bfloat16 g_wt2hi[128 * 512];    // [Ntot=128][K=512]
__device__ __nv_bfloat16 g_wt2lo[128 * 512];

// ---------------- helpers ----------------
__device__ __forceinline__ uint32_t smem_u32(const void* p) {
    uint32_t a;
    asm("{ .reg .u64 t; cvta.to.shared.u64 t, %1; cvt.u32.u64 %0, t; }" : "=r"(a) : "l"(p));
    return a;
}
#define SWZ128(o) ((o) ^ (((o) >> 3) & 0x70))

__device__ __forceinline__ void cp16(uint32_t dst, const void* src) {
    asm volatile("cp.async.cg.shared.global [%0], [%1], 16;" :: "r"(dst), "l"(src));
}
__device__ __forceinline__ void cp_commit() {
    asm volatile("cp.async.commit_group;" ::: "memory");
}
template <int N>
__device__ __forceinline__ void cp_wait() {
    asm volatile("cp.async.wait_group %0;" :: "n"(N) : "memory");
}

__device__ __forceinline__ void ldmx4(uint32_t* r, uint32_t addr) {
    asm volatile("ldmatrix.sync.aligned.m8n8.x4.shared.b16 {%0,%1,%2,%3}, [%4];"
                 : "=r"(r[0]), "=r"(r[1]), "=r"(r[2]), "=r"(r[3]) : "r"(addr));
}
__device__ __forceinline__ void mma16816(float* c, const uint32_t* a, uint32_t b0, uint32_t b1) {
    asm volatile("mma.sync.aligned.m16n8k16.row.col.f32.bf16.bf16.f32 "
                 "{%0,%1,%2,%3}, {%4,%5,%6,%7}, {%8,%9}, {%0,%1,%2,%3};"
                 : "+f"(c[0]), "+f"(c[1]), "+f"(c[2]), "+f"(c[3])
                 : "r"(a[0]), "r"(a[1]), "r"(a[2]), "r"(a[3]), "r"(b0), "r"(b1));
}

// ---------------- fused prep: hist | split(x) | wtsplit1 | wtsplit2 ----------------
#define PREP_HIST_BLKS  1250
#define PREP_SPLIT_BLKS 20000   // N_NODES*F_IN / 256
#define PREP_WT1_BLKS   1024
#define PREP_WT2_BLKS   256
#define PREP_TOTAL (PREP_HIST_BLKS + PREP_SPLIT_BLKS + PREP_WT1_BLKS + PREP_WT2_BLKS)

__global__ void __launch_bounds__(256) prep_kernel(
    const int* __restrict__ dst, const float* __restrict__ x,
    const float* __restrict__ Wl1, const float* __restrict__ Wr1,
    const float* __restrict__ Wl2, const float* __restrict__ Wr2)
{
    int b = blockIdx.x;
    if (b < PREP_HIST_BLKS) {
        int e = b * 256 + threadIdx.x;
        if (e < N_EDGES) atomicAdd(&g_deg[dst[e]], 1);
    } else if (b < PREP_HIST_BLKS + PREP_SPLIT_BLKS) {
        int i = (b - PREP_HIST_BLKS) * 256 + threadIdx.x;
        float v = x[i];
        __nv_bfloat16 h = __float2bfloat16(v);
        g_xhi[i] = h;
        g_xlo[i] = __float2bfloat16(v - __bfloat162float(h));
    } else if (b < PREP_HIST_BLKS + PREP_SPLIT_BLKS + PREP_WT1_BLKS) {
        int i = (b - PREP_HIST_BLKS - PREP_SPLIT_BLKS) * 256 + threadIdx.x;
        int n = i >> 8, k = i & 255;
        float v = (n < 512) ? Wl1[(size_t)k * 512 + n] : Wr1[(size_t)k * 512 + (n - 512)];
        __nv_bfloat16 h = __float2bfloat16(v);
        g_wt1hi[i] = h;
        g_wt1lo[i] = __float2bfloat16(v - __bfloat162float(h));
    } else {
        int i = (b - PREP_HIST_BLKS - PREP_SPLIT_BLKS - PREP_WT1_BLKS) * 256 + threadIdx.x;
        int n = i >> 9, k = i & 511;
        float v = (n < 64) ? Wl2[(size_t)k * 64 + n] : Wr2[(size_t)k * 64 + (n - 64)];
        __nv_bfloat16 h = __float2bfloat16(v);
        g_wt2hi[i] = h;
        g_wt2lo[i] = __float2bfloat16(v - __bfloat162float(h));
    }
}

// ---------------- CSR scan + scatter ----------------
__global__ void scan_kernel() {
    __shared__ int sums[1024];
    const int CH = (N_NODES + 1023) / 1024;
    int t = threadIdx.x;
    int base = t * CH;
    int s = 0;
    for (int i = 0; i < CH; i++) {
        int idx = base + i;
        if (idx < N_NODES) s += g_deg[idx];
    }
    sums[t] = s;
    __syncthreads();
    for (int d = 1; d < 1024; d <<= 1) {
        int v = (t >= d) ? sums[t - d] : 0;
        __syncthreads();
        sums[t] += v;
        __syncthreads();
    }
    int pre = (t == 0) ? 0 : sums[t - 1];
    for (int i = 0; i < CH; i++) {
        int idx = base + i;
        if (idx < N_NODES) {
            g_off[idx] = pre;
            g_cur[idx] = pre;
            pre += g_deg[idx];
        }
    }
    if (t == 0) g_off[N_NODES] = sums[1023];
}

__global__ void scatter_kernel(const int* __restrict__ src, const int* __restrict__ dst) {
    int e = blockIdx.x * blockDim.x + threadIdx.x;
    if (e < N_EDGES) {
        int p = atomicAdd(&g_cur[dst[e]], 1);
        g_esrc[p] = src[e];
    }
}

// ---------------- mma.sync split-bf16 GEMM ----------------
// K-chunk 32, hi/lo interleaved in 128B rows: row r = [hi k0..31 (64B) | lo k0..31 (64B)].
// Stage = A 16KB + B 8KB = 24KB; double-buffered 48KB total -> 3 CTAs/SM (with reg cap).
#define BUF_A 0
#define BUF_B 16384
#define BUF_SZ 24576
#define SM_TOT (2 * BUF_SZ)

__global__ void __launch_bounds__(256, 3) gemm_mma_kernel(
    int M, int K, int ldc,
    const __nv_bfloat16* __restrict__ Ahi, const __nv_bfloat16* __restrict__ Alo,
    const __nv_bfloat16* __restrict__ Bhi, const __nv_bfloat16* __restrict__ Blo,
    float* __restrict__ C)
{
    extern __shared__ char smem[];
    uint32_t sb = smem_u32(smem);
    const int tid = threadIdx.x, wid = tid >> 5, lane = tid & 31;
    const int by = blockIdx.y, bx = blockIdx.x;
    const int warpM = wid & 3, warpN = wid >> 2;   // 4 x 2 warp grid (warp tile 32x32)

    float acc[2][4][4];
#pragma unroll
    for (int a = 0; a < 2; a++)
#pragma unroll
        for (int b = 0; b < 4; b++)
#pragma unroll
            for (int c = 0; c < 4; c++) acc[a][b][c] = 0.f;

    const int nchunks = K >> 5;   // K / 32

    auto issue = [&](int ch) {
        uint32_t buf = sb + (uint32_t)(ch & 1) * BUF_SZ;
        int k0 = ch << 5;
        // A: 128 rows x 8 granules (4 hi + 4 lo), 1024 granules
#pragma unroll
        for (int it = 0; it < 4; it++) {
            int i = tid + 256 * it;
            int row = i >> 3, sub = i & 7;
            int gr = by * 128 + row;
            if (gr >= M) gr = M - 1;   // clamp: garbage rows never stored
            const __nv_bfloat16* srcp = (sub < 4 ? Ahi : Alo) + (size_t)gr * K + k0 + (sub & 3) * 8;
            cp16(buf + BUF_A + SWZ128(row * 128 + sub * 16), srcp);
        }
        // B: 64 rows x 8 granules, 512 granules
#pragma unroll
        for (int it = 0; it < 2; it++) {
            int i = tid + 256 * it;
            int row = i >> 3, sub = i & 7;
            int gn = bx * 64 + row;
            const __nv_bfloat16* srcp = (sub < 4 ? Bhi : Blo) + (size_t)gn * K + k0 + (sub & 3) * 8;
            cp16(buf + BUF_B + SWZ128(row * 128 + sub * 16), srcp);
        }
        cp_commit();
    };

    issue(0);
    for (int ch = 0; ch < nchunks; ch++) {
        if (ch + 1 < nchunks) {
            issue(ch + 1);
            cp_wait<1>();
        } else {
            cp_wait<0>();
        }
        __syncthreads();

        uint32_t buf = sb + (uint32_t)(ch & 1) * BUF_SZ;
#pragma unroll
        for (int ks = 0; ks < 2; ks++) {
            uint32_t ahi[2][4], alo[2][4], bhi[2][4], blo[2][4];
            int colb = ks * 32 + (lane >> 4) * 16;   // hi cols [0,64)
#pragma unroll
            for (int mt = 0; mt < 2; mt++) {
                int rowb = (warpM * 32 + mt * 16 + (lane & 15)) * 128;
                ldmx4(ahi[mt], buf + BUF_A + SWZ128(rowb + colb));
                ldmx4(alo[mt], buf + BUF_A + SWZ128(rowb + 64 + colb));
            }
#pragma unroll
            for (int nt = 0; nt < 2; nt++) {
                int rowb = (warpN * 32 + nt * 16 + (lane & 15)) * 128;
                ldmx4(bhi[nt], buf + BUF_B + SWZ128(rowb + colb));
                ldmx4(blo[nt], buf + BUF_B + SWZ128(rowb + 64 + colb));
            }
#pragma unroll
            for (int mt = 0; mt < 2; mt++)
#pragma unroll
                for (int nt = 0; nt < 2; nt++)
#pragma unroll
                    for (int hf = 0; hf < 2; hf++) {
                        float* c = acc[mt][nt * 2 + hf];
                        mma16816(c, ahi[mt], bhi[nt][hf], bhi[nt][hf + 2]);
                        mma16816(c, ahi[mt], blo[nt][hf], blo[nt][hf + 2]);
                        mma16816(c, alo[mt], bhi[nt][hf], bhi[nt][hf + 2]);
                    }
        }
        __syncthreads();
    }

    // epilogue: stage fp32 tile in smem, coalesced store
    float* stage = (float*)smem;
    {
        int r0 = lane >> 2, cb = (lane & 3) * 2;
#pragma unroll
        for (int mt = 0; mt < 2; mt++)
#pragma unroll
            for (int j = 0; j < 4; j++) {
                int col = warpN * 32 + (j >> 1) * 16 + (j & 1) * 8 + cb;
                float* st = stage + (warpM * 32 + mt * 16 + r0) * 64 + col;
                st[0]          = acc[mt][j][0];
                st[1]          = acc[mt][j][1];
                st[8 * 64]     = acc[mt][j][2];
                st[8 * 64 + 1] = acc[mt][j][3];
            }
    }
    __syncthreads();
    for (int i = tid; i < 2048; i += 256) {
        int row = i >> 4, c4 = (i & 15) << 2;
        int gr = by * 128 + row;
        if (gr < M)
            *(float4*)(C + (size_t)gr * ldc + bx * 64 + c4) = *(float4*)(stage + row * 64 + c4);
    }
}

// ---------------- layer 1: fused node kernel, 1 warp/head, lane-parallel indices ----------------
__global__ void __launch_bounds__(256) node1_fused_kernel(
    const float* __restrict__ att1, const float* __restrict__ b1)
{
    int n = blockIdx.x;
    int h = threadIdx.x >> 5, lane = threadIdx.x & 31;
    int beg = g_off[n], end = g_off[n + 1];
    int c0 = h * 64 + lane;

    float xr0 = g_xlr1[(size_t)n * 1024 + 512 + c0];
    float xr1 = g_xlr1[(size_t)n * 1024 + 512 + c0 + 32];
    float at0 = att1[c0], at1 = att1[c0 + 32];

    float m = -CUDART_INF_F, ssum = 0.f, acc0 = 0.f, acc1 = 0.f;

    for (int r = beg; r < end; r += 32) {
        int cnt = min(32, end - r);
        int sidx = (lane < cnt) ? g_esrc[r + lane] : 0;
        for (int j = 0; j < cnt; j += 8) {
            float xa[8], xb[8], sc[8];
#pragma unroll
            for (int k = 0; k < 8; k++) {
                int sn = __shfl_sync(0xffffffffu, sidx, j + k);
                const float* p = g_xlr1 + (size_t)sn * 1024 + h * 64;
                bool valid = (j + k) < cnt;
                xa[k] = valid ? p[lane] : 0.f;
                xb[k] = valid ? p[lane + 32] : 0.f;
            }
#pragma unroll
            for (int k = 0; k < 8; k++) {
                float u = xa[k] + xr0; u = u > 0.f ? u : NEG_SLOPE * u;
                float v = xb[k] + xr1; v = v > 0.f ? v : NEG_SLOPE * v;
                sc[k] = at0 * u + at1 * v;
            }
#pragma unroll
            for (int o = 16; o; o >>= 1)
#pragma unroll
                for (int k = 0; k < 8; k++)
                    sc[k] += __shfl_xor_sync(0xffffffffu, sc[k], o);
            float mn = m;
#pragma unroll
            for (int k = 0; k < 8; k++)
                if ((j + k) < cnt) mn = fmaxf(mn, sc[k]);
            float scale = __expf(m - mn);
            float wsum = 0.f, a0 = 0.f, a1 = 0.f;
#pragma unroll
            for (int k = 0; k < 8; k++) {
                float w = ((j + k) < cnt) ? __expf(sc[k] - mn) : 0.f;
                wsum += w;
                a0 += w * xa[k];
                a1 += w * xb[k];
            }
            ssum = ssum * scale + wsum;
            acc0 = acc0 * scale + a0;
            acc1 = acc1 * scale + a1;
            m = mn;
        }
    }

    float inv = 1.f / (ssum + SM_EPS);
    float v0 = acc0 * inv + b1[c0];
    float v1 = acc1 * inv + b1[c0 + 32];
    v0 = v0 > 0.f ? v0 : __expf(v0) - 1.f;
    v1 = v1 > 0.f ? v1 : __expf(v1) - 1.f;
    size_t o0 = (size_t)n * HC1 + c0, o1 = o0 + 32;
    __nv_bfloat16 h0 = __float2bfloat16(v0), h1 = __float2bfloat16(v1);
    g_hhi[o0] = h0; g_hlo[o0] = __float2bfloat16(v0 - __bfloat162float(h0));
    g_hhi[o1] = h1; g_hlo[o1] = __float2bfloat16(v1 - __bfloat162float(h1));
}

// ---------------- layer 2: fused node kernel, 1 warp/node ----------------
__global__ void __launch_bounds__(256) node2_fused_kernel(
    const float* __restrict__ att2, const float* __restrict__ b2,
    float* __restrict__ out)
{
    int n = blockIdx.x * 8 + (threadIdx.x >> 5);
    if (n >= N_NODES) return;
    int lane = threadIdx.x & 31;
    int beg = g_off[n], end = g_off[n + 1];

    float xr0 = g_xlr2[(size_t)n * 128 + 64 + lane];
    float xr1 = g_xlr2[(size_t)n * 128 + 64 + lane + 32];
    float at0 = att2[lane], at1 = att2[lane + 32];

    float m = -CUDART_INF_F, ssum = 0.f, acc0 = 0.f, acc1 = 0.f;

    for (int r = beg; r < end; r += 32) {
        int cnt = min(32, end - r);
        int sidx = (lane < cnt) ? g_esrc[r + lane] : 0;
        for (int j = 0; j < cnt; j += 8) {
            float xa[8], xb[8], sc[8];
#pragma unroll
            for (int k = 0; k < 8; k++) {
                int sn = __shfl_sync(0xffffffffu, sidx, j + k);
                const float* p = g_xlr2 + (size_t)sn * 128;
                bool valid = (j + k) < cnt;
                xa[k] = valid ? p[lane] : 0.f;
                xb[k] = valid ? p[lane + 32] : 0.f;
            }
#pragma unroll
            for (int k = 0; k < 8; k++) {
                float u = xa[k] + xr0; u = u > 0.f ? u : NEG_SLOPE * u;
                float v = xb[k] + xr1; v = v > 0.f ? v : NEG_SLOPE * v;
                sc[k] = at0 * u + at1 * v;
            }
#pragma unroll
            for (int o = 16; o; o >>= 1)
#pragma unroll
                for (int k = 0; k < 8; k++)
                    sc[k] += __shfl_xor_sync(0xffffffffu, sc[k], o);
            float mn = m;
#pragma unroll
            for (int k = 0; k < 8; k++)
                if ((j + k) < cnt) mn = fmaxf(mn, sc[k]);
            float scale = __expf(m - mn);
            float wsum = 0.f, a0 = 0.f, a1 = 0.f;
#pragma unroll
            for (int k = 0; k < 8; k++) {
                float w = ((j + k) < cnt) ? __expf(sc[k] - mn) : 0.f;
                wsum += w;
                a0 += w * xa[k];
                a1 += w * xb[k];
            }
            ssum = ssum * scale + wsum;
            acc0 = acc0 * scale + a0;
            acc1 = acc1 * scale + a1;
            m = mn;
        }
    }

    float inv = 1.f / (ssum + SM_EPS);
    out[(size_t)n * NCLS + lane]      = acc0 * inv + b2[lane];
    out[(size_t)n * NCLS + lane + 32] = acc1 * inv + b2[lane + 32];
}

// ---------------- launch ----------------
extern "C" void kernel_launch(void* const* d_in, const int* in_sizes, int n_in,
                              void* d_out, int out_size)
{
    (void)in_sizes; (void)n_in; (void)out_size;
    const float* x    = (const float*)d_in[0];
    const int*   ei   = (const int*)d_in[1];
    const int*   src  = ei;
    const int*   dst  = ei + N_EDGES;
    const float* Wl1  = (const float*)d_in[2];
    const float* Wr1  = (const float*)d_in[3];
    const float* att1 = (const float*)d_in[4];
    const float* b1   = (const float*)d_in[5];
    const float* Wl2  = (const float*)d_in[6];
    const float* Wr2  = (const float*)d_in[7];
    const float* att2 = (const float*)d_in[8];
    const float* b2   = (const float*)d_in[9];
    float* out = (float*)d_out;

    cudaFuncSetAttribute(gemm_mma_kernel, cudaFuncAttributeMaxDynamicSharedMemorySize, SM_TOT);

    void *p_deg, *p_xlr1, *p_xlr2;
    void *p_xhi, *p_xlo, *p_hhi, *p_hlo, *p_w1h, *p_w1l, *p_w2h, *p_w2l;
    cudaGetSymbolAddress(&p_deg, g_deg);
    cudaGetSymbolAddress(&p_xlr1, g_xlr1);
    cudaGetSymbolAddress(&p_xlr2, g_xlr2);
    cudaGetSymbolAddress(&p_xhi, g_xhi);
    cudaGetSymbolAddress(&p_xlo, g_xlo);
    cudaGetSymbolAddress(&p_hhi, g_hhi);
    cudaGetSymbolAddress(&p_hlo, g_hlo);
    cudaGetSymbolAddress(&p_w1h, g_wt1hi);
    cudaGetSymbolAddress(&p_w1l, g_wt1lo);
    cudaGetSymbolAddress(&p_w2h, g_wt2hi);
    cudaGetSymbolAddress(&p_w2l, g_wt2lo);

    // (1) zero degree histogram
    cudaMemsetAsync(p_deg, 0, N_NODES * sizeof(int), 0);
    // (2) fused prep: hist | x-split | wt1 transpose-split | wt2 transpose-split
    prep_kernel<<<PREP_TOTAL, 256>>>(dst, x, Wl1, Wr1, Wl2, Wr2);
    // (3) CSR scan, (4) scatter
    scan_kernel<<<1, 1024>>>();
    scatter_kernel<<<(N_EDGES + 255) / 256, 256>>>(src, dst);

    // (5) layer-1 projections: g_xlr1 [N,1024]  <-- profiled slot
    {
        dim3 grid(1024 / 64, (N_NODES + 127) / 128);
        gemm_mma_kernel<<<grid, 256, SM_TOT>>>(
            N_NODES, 256, 1024,
            (const __nv_bfloat16*)p_xhi, (const __nv_bfloat16*)p_xlo,
            (const __nv_bfloat16*)p_w1h, (const __nv_bfloat16*)p_w1l,
            (float*)p_xlr1);
    }
    // (6) layer-1 node phase
    node1_fused_kernel<<<N_NODES, 256>>>(att1, b1);

    // (7) layer-2 projections: g_xlr2 [N,128]
    {
        dim3 grid(128 / 64, (N_NODES + 127) / 128);
        gemm_mma_kernel<<<grid, 256, SM_TOT>>>(
            N_NODES, 512, 128,
            (const __nv_bfloat16*)p_hhi, (const __nv_bfloat16*)p_hlo,
            (const __nv_bfloat16*)p_w2h, (const __nv_bfloat16*)p_w2l,
            (float*)p_xlr2);
    }
    // (8) layer-2 node phase -> output
    node2_fused_kernel<<<(N_NODES + 7) / 8, 256>>>(att2, b2, out);
}

// round 15
// speedup vs baseline: 1.0003x; 1.0003x over previous
#include <cuda_runtime.h>
#include <cuda_bf16.h>
#include <math_constants.h>
#include <cstdint>

// ---------------- problem constants ----------------
#define N_NODES 20000
#define N_EDGES 320000
#define F_IN    256
#define HIDC    64
#define HEADS   8
#define NCLS    64
#define HC1     (HEADS*HIDC)      // 512
#define NEG_SLOPE 0.2f
#define SM_EPS  1e-16f

typedef unsigned long long u64;

// ---------------- scratch (static device globals; no allocs) ----------------
__device__ float g_xlr1[(size_t)N_NODES * 1024];   // [N][xl1(512) | xr1(512)]
__device__ float g_xlr2[(size_t)N_NODES * 128];    // [N][xl2(64) | xr2(64)]
__device__ int   g_deg[N_NODES];
__device__ int   g_off[N_NODES + 1];
__device__ int   g_cur[N_NODES];
__device__ int   g_esrc[N_EDGES];                  // CSR-ordered source node ids

// bf16 split operands
__device__ __nv_bfloat16 g_xhi[(size_t)N_NODES * F_IN];
__device__ __nv_bfloat16 g_xlo[(size_t)N_NODES * F_IN];
__device__ __nv_bfloat16 g_hhi[(size_t)N_NODES * HC1];   // written by node1 epilogue
__device__ __nv_bfloat16 g_hlo[(size_t)N_NODES * HC1];
__device__ __nv_bfloat16 g_wt1hi[1024 * 256];   // [Ntot=1024][K=256] (W^T, K-contig)
__device__ __nv_bfloat16 g_wt1lo[1024 * 256];
__device__ __nv_bfloat16 g_wt2hi[128 * 512];    // [Ntot=128][K=512]
__device__ __nv_bfloat16 g_wt2lo[128 * 512];

// ---------------- helpers ----------------
__device__ __forceinline__ uint32_t smem_u32(const void* p) {
    uint32_t a;
    asm("{ .reg .u64 t; cvta.to.shared.u64 t, %1; cvt.u32.u64 %0, t; }" : "=r"(a) : "l"(p));
    return a;
}
#define SWZ128(o) ((o) ^ (((o) >> 3) & 0x70))

__device__ __forceinline__ void cp16(uint32_t dst, const void* src) {
    asm volatile("cp.async.cg.shared.global [%0], [%1], 16;" :: "r"(dst), "l"(src));
}
__device__ __forceinline__ void cp_commit() {
    asm volatile("cp.async.commit_group;" ::: "memory");
}
template <int N>
__device__ __forceinline__ void cp_wait() {
    asm volatile("cp.async.wait_group %0;" :: "n"(N) : "memory");
}

__device__ __forceinline__ void ldmx4(uint32_t* r, uint32_t addr) {
    asm volatile("ldmatrix.sync.aligned.m8n8.x4.shared.b16 {%0,%1,%2,%3}, [%4];"
                 : "=r"(r[0]), "=r"(r[1]), "=r"(r[2]), "=r"(r[3]) : "r"(addr));
}
__device__ __forceinline__ void mma16816(float* c, const uint32_t* a, uint32_t b0, uint32_t b1) {
    asm volatile("mma.sync.aligned.m16n8k16.row.col.f32.bf16.bf16.f32 "
                 "{%0,%1,%2,%3}, {%4,%5,%6,%7}, {%8,%9}, {%0,%1,%2,%3};"
                 : "+f"(c[0]), "+f"(c[1]), "+f"(c[2]), "+f"(c[3])
                 : "r"(a[0]), "r"(a[1]), "r"(a[2]), "r"(a[3]), "r"(b0), "r"(b1));
}

// ---------------- fused prep: hist | split(x) | wtsplit1 | wtsplit2 ----------------
#define PREP_HIST_BLKS  1250
#define PREP_SPLIT_BLKS 20000   // N_NODES*F_IN / 256
#define PREP_WT1_BLKS   1024
#define PREP_WT2_BLKS   256
#define PREP_TOTAL (PREP_HIST_BLKS + PREP_SPLIT_BLKS + PREP_WT1_BLKS + PREP_WT2_BLKS)

__global__ void __launch_bounds__(256) prep_kernel(
    const int* __restrict__ dst, const float* __restrict__ x,
    const float* __restrict__ Wl1, const float* __restrict__ Wr1,
    const float* __restrict__ Wl2, const float* __restrict__ Wr2)
{
    int b = blockIdx.x;
    if (b < PREP_HIST_BLKS) {
        int e = b * 256 + threadIdx.x;
        if (e < N_EDGES) atomicAdd(&g_deg[dst[e]], 1);
    } else if (b < PREP_HIST_BLKS + PREP_SPLIT_BLKS) {
        int i = (b - PREP_HIST_BLKS) * 256 + threadIdx.x;
        float v = x[i];
        __nv_bfloat16 h = __float2bfloat16(v);
        g_xhi[i] = h;
        g_xlo[i] = __float2bfloat16(v - __bfloat162float(h));
    } else if (b < PREP_HIST_BLKS + PREP_SPLIT_BLKS + PREP_WT1_BLKS) {
        int i = (b - PREP_HIST_BLKS - PREP_SPLIT_BLKS) * 256 + threadIdx.x;
        int n = i >> 8, k = i & 255;
        float v = (n < 512) ? Wl1[(size_t)k * 512 + n] : Wr1[(size_t)k * 512 + (n - 512)];
        __nv_bfloat16 h = __float2bfloat16(v);
        g_wt1hi[i] = h;
        g_wt1lo[i] = __float2bfloat16(v - __bfloat162float(h));
    } else {
        int i = (b - PREP_HIST_BLKS - PREP_SPLIT_BLKS - PREP_WT1_BLKS) * 256 + threadIdx.x;
        int n = i >> 9, k = i & 511;
        float v = (n < 64) ? Wl2[(size_t)k * 64 + n] : Wr2[(size_t)k * 64 + (n - 64)];
        __nv_bfloat16 h = __float2bfloat16(v);
        g_wt2hi[i] = h;
        g_wt2lo[i] = __float2bfloat16(v - __bfloat162float(h));
    }
}

// ---------------- CSR scan + scatter ----------------
__global__ void scan_kernel() {
    __shared__ int sums[1024];
    const int CH = (N_NODES + 1023) / 1024;
    int t = threadIdx.x;
    int base = t * CH;
    int s = 0;
    for (int i = 0; i < CH; i++) {
        int idx = base + i;
        if (idx < N_NODES) s += g_deg[idx];
    }
    sums[t] = s;
    __syncthreads();
    for (int d = 1; d < 1024; d <<= 1) {
        int v = (t >= d) ? sums[t - d] : 0;
        __syncthreads();
        sums[t] += v;
        __syncthreads();
    }
    int pre = (t == 0) ? 0 : sums[t - 1];
    for (int i = 0; i < CH; i++) {
        int idx = base + i;
        if (idx < N_NODES) {
            g_off[idx] = pre;
            g_cur[idx] = pre;
            pre += g_deg[idx];
        }
    }
    if (t == 0) g_off[N_NODES] = sums[1023];
}

__global__ void scatter_kernel(const int* __restrict__ src, const int* __restrict__ dst) {
    int e = blockIdx.x * blockDim.x + threadIdx.x;
    if (e < N_EDGES) {
        int p = atomicAdd(&g_cur[dst[e]], 1);
        g_esrc[p] = src[e];
    }
}

// ---------------- mma.sync split-bf16 GEMM ----------------
// K-chunk 32, hi/lo interleaved in 128B rows; 3-stage cp.async pipeline (2-chunk lookahead).
// Stage = A 16KB + B 8KB = 24KB; 3 stages = 72KB -> 3 CTAs/SM (with reg cap).
#define BUF_A 0
#define BUF_B 16384
#define BUF_SZ 24576
#define SM_TOT (3 * BUF_SZ)

__global__ void __launch_bounds__(256, 3) gemm_mma_kernel(
    int M, int K, int ldc,
    const __nv_bfloat16* __restrict__ Ahi, const __nv_bfloat16* __restrict__ Alo,
    const __nv_bfloat16* __restrict__ Bhi, const __nv_bfloat16* __restrict__ Blo,
    float* __restrict__ C)
{
    extern __shared__ char smem[];
    uint32_t sb = smem_u32(smem);
    const int tid = threadIdx.x, wid = tid >> 5, lane = tid & 31;
    const int by = blockIdx.y, bx = blockIdx.x;
    const int warpM = wid & 3, warpN = wid >> 2;   // 4 x 2 warp grid (warp tile 32x32)

    float acc[2][4][4];
#pragma unroll
    for (int a = 0; a < 2; a++)
#pragma unroll
        for (int b = 0; b < 4; b++)
#pragma unroll
            for (int c = 0; c < 4; c++) acc[a][b][c] = 0.f;

    const int nchunks = K >> 5;   // K / 32

    auto issue = [&](int ch) {
        uint32_t buf = sb + (uint32_t)(ch % 3) * BUF_SZ;
        int k0 = ch << 5;
        // A: 128 rows x 8 granules (4 hi + 4 lo), 1024 granules
#pragma unroll
        for (int it = 0; it < 4; it++) {
            int i = tid + 256 * it;
            int row = i >> 3, sub = i & 7;
            int gr = by * 128 + row;
            if (gr >= M) gr = M - 1;   // clamp: garbage rows never stored
            const __nv_bfloat16* srcp = (sub < 4 ? Ahi : Alo) + (size_t)gr * K + k0 + (sub & 3) * 8;
            cp16(buf + BUF_A + SWZ128(row * 128 + sub * 16), srcp);
        }
        // B: 64 rows x 8 granules, 512 granules
#pragma unroll
        for (int it = 0; it < 2; it++) {
            int i = tid + 256 * it;
            int row = i >> 3, sub = i & 7;
            int gn = bx * 64 + row;
            const __nv_bfloat16* srcp = (sub < 4 ? Bhi : Blo) + (size_t)gn * K + k0 + (sub & 3) * 8;
            cp16(buf + BUF_B + SWZ128(row * 128 + sub * 16), srcp);
        }
        cp_commit();
    };

    issue(0);
    if (nchunks > 1) issue(1);
    for (int ch = 0; ch < nchunks; ch++) {
        if (ch + 2 < nchunks) {
            issue(ch + 2);
            cp_wait<2>();
        } else if (ch + 1 < nchunks) {
            cp_wait<1>();
        } else {
            cp_wait<0>();
        }
        __syncthreads();

        uint32_t buf = sb + (uint32_t)(ch % 3) * BUF_SZ;
#pragma unroll
        for (int ks = 0; ks < 2; ks++) {
            uint32_t ahi[2][4], alo[2][4], bhi[2][4], blo[2][4];
            int colb = ks * 32 + (lane >> 4) * 16;   // hi cols [0,64)
#pragma unroll
            for (int mt = 0; mt < 2; mt++) {
                int rowb = (warpM * 32 + mt * 16 + (lane & 15)) * 128;
                ldmx4(ahi[mt], buf + BUF_A + SWZ128(rowb + colb));
                ldmx4(alo[mt], buf + BUF_A + SWZ128(rowb + 64 + colb));
            }
#pragma unroll
            for (int nt = 0; nt < 2; nt++) {
                int rowb = (warpN * 32 + nt * 16 + (lane & 15)) * 128;
                ldmx4(bhi[nt], buf + BUF_B + SWZ128(rowb + colb));
                ldmx4(blo[nt], buf + BUF_B + SWZ128(rowb + 64 + colb));
            }
#pragma unroll
            for (int mt = 0; mt < 2; mt++)
#pragma unroll
                for (int nt = 0; nt < 2; nt++)
#pragma unroll
                    for (int hf = 0; hf < 2; hf++) {
                        float* c = acc[mt][nt * 2 + hf];
                        mma16816(c, ahi[mt], bhi[nt][hf], bhi[nt][hf + 2]);
                        mma16816(c, ahi[mt], blo[nt][hf], blo[nt][hf + 2]);
                        mma16816(c, alo[mt], bhi[nt][hf], bhi[nt][hf + 2]);
                    }
        }
        __syncthreads();   // buffer (ch%3) reused by issue(ch+3) next iteration
    }

    // epilogue: stage fp32 tile in smem, coalesced store
    float* stage = (float*)smem;
    {
        int r0 = lane >> 2, cb = (lane & 3) * 2;
#pragma unroll
        for (int mt = 0; mt < 2; mt++)
#pragma unroll
            for (int j = 0; j < 4; j++) {
                int col = warpN * 32 + (j >> 1) * 16 + (j & 1) * 8 + cb;
                float* st = stage + (warpM * 32 + mt * 16 + r0) * 64 + col;
                st[0]          = acc[mt][j][0];
                st[1]          = acc[mt][j][1];
                st[8 * 64]     = acc[mt][j][2];
                st[8 * 64 + 1] = acc[mt][j][3];
            }
    }
    __syncthreads();
    for (int i = tid; i < 2048; i += 256) {
        int row = i >> 4, c4 = (i & 15) << 2;
        int gr = by * 128 + row;
        if (gr < M)
            *(float4*)(C + (size_t)gr * ldc + bx * 64 + c4) = *(float4*)(stage + row * 64 + c4);
    }
}

// ---------------- layer 1: fused node kernel, 1 warp/head, lane-parallel indices ----------------
__global__ void __launch_bounds__(256) node1_fused_kernel(
    const float* __restrict__ att1, const float* __restrict__ b1)
{
    int n = blockIdx.x;
    int h = threadIdx.x >> 5, lane = threadIdx.x & 31;
    int beg = g_off[n], end = g_off[n + 1];
    int c0 = h * 64 + lane;

    float xr0 = g_xlr1[(size_t)n * 1024 + 512 + c0];
    float xr1 = g_xlr1[(size_t)n * 1024 + 512 + c0 + 32];
    float at0 = att1[c0], at1 = att1[c0 + 32];

    float m = -CUDART_INF_F, ssum = 0.f, acc0 = 0.f, acc1 = 0.f;

    for (int r = beg; r < end; r += 32) {
        int cnt = min(32, end - r);
        int sidx = (lane < cnt) ? g_esrc[r + lane] : 0;
        for (int j = 0; j < cnt; j += 8) {
            float xa[8], xb[8], sc[8];
#pragma unroll
            for (int k = 0; k < 8; k++) {
                int sn = __shfl_sync(0xffffffffu, sidx, j + k);
                const float* p = g_xlr1 + (size_t)sn * 1024 + h * 64;
                bool valid = (j + k) < cnt;
                xa[k] = valid ? p[lane] : 0.f;
                xb[k] = valid ? p[lane + 32] : 0.f;
            }
#pragma unroll
            for (int k = 0; k < 8; k++) {
                float u = xa[k] + xr0; u = u > 0.f ? u : NEG_SLOPE * u;
                float v = xb[k] + xr1; v = v > 0.f ? v : NEG_SLOPE * v;
                sc[k] = at0 * u + at1 * v;
            }
#pragma unroll
            for (int o = 16; o; o >>= 1)
#pragma unroll
                for (int k = 0; k < 8; k++)
                    sc[k] += __shfl_xor_sync(0xffffffffu, sc[k], o);
            float mn = m;
#pragma unroll
            for (int k = 0; k < 8; k++)
                if ((j + k) < cnt) mn = fmaxf(mn, sc[k]);
            float scale = __expf(m - mn);
            float wsum = 0.f, a0 = 0.f, a1 = 0.f;
#pragma unroll
            for (int k = 0; k < 8; k++) {
                float w = ((j + k) < cnt) ? __expf(sc[k] - mn) : 0.f;
                wsum += w;
                a0 += w * xa[k];
                a1 += w * xb[k];
            }
            ssum = ssum * scale + wsum;
            acc0 = acc0 * scale + a0;
            acc1 = acc1 * scale + a1;
            m = mn;
        }
    }

    float inv = 1.f / (ssum + SM_EPS);
    float v0 = acc0 * inv + b1[c0];
    float v1 = acc1 * inv + b1[c0 + 32];
    v0 = v0 > 0.f ? v0 : __expf(v0) - 1.f;
    v1 = v1 > 0.f ? v1 : __expf(v1) - 1.f;
    size_t o0 = (size_t)n * HC1 + c0, o1 = o0 + 32;
    __nv_bfloat16 h0 = __float2bfloat16(v0), h1 = __float2bfloat16(v1);
    g_hhi[o0] = h0; g_hlo[o0] = __float2bfloat16(v0 - __bfloat162float(h0));
    g_hhi[o1] = h1; g_hlo[o1] = __float2bfloat16(v1 - __bfloat162float(h1));
}

// ---------------- layer 2: fused node kernel, 1 warp/node ----------------
__global__ void __launch_bounds__(256) node2_fused_kernel(
    const float* __restrict__ att2, const float* __restrict__ b2,
    float* __restrict__ out)
{
    int n = blockIdx.x * 8 + (threadIdx.x >> 5);
    if (n >= N_NODES) return;
    int lane = threadIdx.x & 31;
    int beg = g_off[n], end = g_off[n + 1];

    float xr0 = g_xlr2[(size_t)n * 128 + 64 + lane];
    float xr1 = g_xlr2[(size_t)n * 128 + 64 + lane + 32];
    float at0 = att2[lane], at1 = att2[lane + 32];

    float m = -CUDART_INF_F, ssum = 0.f, acc0 = 0.f, acc1 = 0.f;

    for (int r = beg; r < end; r += 32) {
        int cnt = min(32, end - r);
        int sidx = (lane < cnt) ? g_esrc[r + lane] : 0;
        for (int j = 0; j < cnt; j += 8) {
            float xa[8], xb[8], sc[8];
#pragma unroll
            for (int k = 0; k < 8; k++) {
                int sn = __shfl_sync(0xffffffffu, sidx, j + k);
                const float* p = g_xlr2 + (size_t)sn * 128;
                bool valid = (j + k) < cnt;
                xa[k] = valid ? p[lane] : 0.f;
                xb[k] = valid ? p[lane + 32] : 0.f;
            }
#pragma unroll
            for (int k = 0; k < 8; k++) {
                float u = xa[k] + xr0; u = u > 0.f ? u : NEG_SLOPE * u;
                float v = xb[k] + xr1; v = v > 0.f ? v : NEG_SLOPE * v;
                sc[k] = at0 * u + at1 * v;
            }
#pragma unroll
            for (int o = 16; o; o >>= 1)
#pragma unroll
                for (int k = 0; k < 8; k++)
                    sc[k] += __shfl_xor_sync(0xffffffffu, sc[k], o);
            float mn = m;
#pragma unroll
            for (int k = 0; k < 8; k++)
                if ((j + k) < cnt) mn = fmaxf(mn, sc[k]);
            float scale = __expf(m - mn);
            float wsum = 0.f, a0 = 0.f, a1 = 0.f;
#pragma unroll
            for (int k = 0; k < 8; k++) {
                float w = ((j + k) < cnt) ? __expf(sc[k] - mn) : 0.f;
                wsum += w;
                a0 += w * xa[k];
                a1 += w * xb[k];
            }
            ssum = ssum * scale + wsum;
            acc0 = acc0 * scale + a0;
            acc1 = acc1 * scale + a1;
            m = mn;
        }
    }

    float inv = 1.f / (ssum + SM_EPS);
    out[(size_t)n * NCLS + lane]      = acc0 * inv + b2[lane];
    out[(size_t)n * NCLS + lane + 32] = acc1 * inv + b2[lane + 32];
}

// ---------------- launch ----------------
extern "C" void kernel_launch(void* const* d_in, const int* in_sizes, int n_in,
                              void* d_out, int out_size)
{
    (void)in_sizes; (void)n_in; (void)out_size;
    const float* x    = (const float*)d_in[0];
    const int*   ei   = (const int*)d_in[1];
    const int*   src  = ei;
    const int*   dst  = ei + N_EDGES;
    const float* Wl1  = (const float*)d_in[2];
    const float* Wr1  = (const float*)d_in[3];
    const float* att1 = (const float*)d_in[4];
    const float* b1   = (const float*)d_in[5];
    const float* Wl2  = (const float*)d_in[6];
    const float* Wr2  = (const float*)d_in[7];
    const float* att2 = (const float*)d_in[8];
    const float* b2   = (const float*)d_in[9];
    float* out = (float*)d_out;

    cudaFuncSetAttribute(gemm_mma_kernel, cudaFuncAttributeMaxDynamicSharedMemorySize, SM_TOT);

    void *p_deg, *p_xlr1, *p_xlr2;
    void *p_xhi, *p_xlo, *p_hhi, *p_hlo, *p_w1h, *p_w1l, *p_w2h, *p_w2l;
    cudaGetSymbolAddress(&p_deg, g_deg);
    cudaGetSymbolAddress(&p_xlr1, g_xlr1);
    cudaGetSymbolAddress(&p_xlr2, g_xlr2);
    cudaGetSymbolAddress(&p_xhi, g_xhi);
    cudaGetSymbolAddress(&p_xlo, g_xlo);
    cudaGetSymbolAddress(&p_hhi, g_hhi);
    cudaGetSymbolAddress(&p_hlo, g_hlo);
    cudaGetSymbolAddress(&p_w1h, g_wt1hi);
    cudaGetSymbolAddress(&p_w1l, g_wt1lo);
    cudaGetSymbolAddress(&p_w2h, g_wt2hi);
    cudaGetSymbolAddress(&p_w2l, g_wt2lo);

    // (1) zero degree histogram
    cudaMemsetAsync(p_deg, 0, N_NODES * sizeof(int), 0);
    // (2) fused prep: hist | x-split | wt1 transpose-split | wt2 transpose-split
    prep_kernel<<<PREP_TOTAL, 256>>>(dst, x, Wl1, Wr1, Wl2, Wr2);
    // (3) CSR scan, (4) scatter
    scan_kernel<<<1, 1024>>>();
    scatter_kernel<<<(N_EDGES + 255) / 256, 256>>>(src, dst);

    // (5) layer-1 projections: g_xlr1 [N,1024]  <-- profiled slot
    {
        dim3 grid(1024 / 64, (N_NODES + 127) / 128);
        gemm_mma_kernel<<<grid, 256, SM_TOT>>>(
            N_NODES, 256, 1024,
            (const __nv_bfloat16*)p_xhi, (const __nv_bfloat16*)p_xlo,
            (const __nv_bfloat16*)p_w1h, (const __nv_bfloat16*)p_w1l,
            (float*)p_xlr1);
    }
    // (6) layer-1 node phase
    node1_fused_kernel<<<N_NODES, 256>>>(att1, b1);

    // (7) layer-2 projections: g_xlr2 [N,128]
    {
        dim3 grid(128 / 64, (N_NODES + 127) / 128);
        gemm_mma_kernel<<<grid, 256, SM_TOT>>>(
            N_NODES, 512, 128,
            (const __nv_bfloat16*)p_hhi, (const __nv_bfloat16*)p_hlo,
            (const __nv_bfloat16*)p_w2h, (const __nv_bfloat16*)p_w2l,
            (float*)p_xlr2);
    }
    // (8) layer-2 node phase -> output
    node2_fused_kernel<<<(N_NODES + 7) / 8, 256>>>(att2, b2, out);
}

// round 16
// speedup vs baseline: 1.0895x; 1.0892x over previous
#include <cuda_runtime.h>
#include <cuda_bf16.h>
#include <math_constants.h>
#include <cstdint>

// ---------------- problem constants ----------------
#define N_NODES 20000
#define N_EDGES 320000
#define F_IN    256
#define HIDC    64
#define HEADS   8
#define NCLS    64
#define HC1     (HEADS*HIDC)      // 512
#define NEG_SLOPE 0.2f
#define SM_EPS  1e-16f

typedef unsigned long long u64;

// ---------------- scratch (static device globals; no allocs) ----------------
__device__ float g_xlr1[(size_t)N_NODES * 1024];   // [N][xl1(512) | xr1(512)]
__device__ float g_xlr2[(size_t)N_NODES * 128];    // [N][xl2(64) | xr2(64)]
__device__ int   g_deg[N_NODES];                   // zero-initialized; re-zeroed by node2
__device__ int   g_off[N_NODES + 1];
__device__ int   g_cur[N_NODES];
__device__ int   g_esrc[N_EDGES];                  // CSR-ordered source node ids

// bf16 split operands
__device__ __nv_bfloat16 g_xhi[(size_t)N_NODES * F_IN];
__device__ __nv_bfloat16 g_xlo[(size_t)N_NODES * F_IN];
__device__ __nv_bfloat16 g_hhi[(size_t)N_NODES * HC1];   // written by node1 epilogue
__device__ __nv_bfloat16 g_hlo[(size_t)N_NODES * HC1];
__device__ __nv_bfloat16 g_wt1hi[1024 * 256];   // [Ntot=1024][K=256] (W^T, K-contig)
__device__ __nv_bfloat16 g_wt1lo[1024 * 256];
__device__ __nv_bfloat16 g_wt2hi[128 * 512];    // [Ntot=128][K=512]
__device__ __nv_bfloat16 g_wt2lo[128 * 512];

// ---------------- helpers ----------------
__device__ __forceinline__ uint32_t smem_u32(const void* p) {
    uint32_t a;
    asm("{ .reg .u64 t; cvta.to.shared.u64 t, %1; cvt.u32.u64 %0, t; }" : "=r"(a) : "l"(p));
    return a;
}
#define SWZ128(o) ((o) ^ (((o) >> 3) & 0x70))

__device__ __forceinline__ void cp16(uint32_t dst, const void* src) {
    asm volatile("cp.async.cg.shared.global [%0], [%1], 16;" :: "r"(dst), "l"(src));
}
__device__ __forceinline__ void cp_commit() {
    asm volatile("cp.async.commit_group;" ::: "memory");
}
template <int N>
__device__ __forceinline__ void cp_wait() {
    asm volatile("cp.async.wait_group %0;" :: "n"(N) : "memory");
}

__device__ __forceinline__ void ldmx4(uint32_t* r, uint32_t addr) {
    asm volatile("ldmatrix.sync.aligned.m8n8.x4.shared.b16 {%0,%1,%2,%3}, [%4];"
                 : "=r"(r[0]), "=r"(r[1]), "=r"(r[2]), "=r"(r[3]) : "r"(addr));
}
__device__ __forceinline__ void mma16816(float* c, const uint32_t* a, uint32_t b0, uint32_t b1) {
    asm volatile("mma.sync.aligned.m16n8k16.row.col.f32.bf16.bf16.f32 "
                 "{%0,%1,%2,%3}, {%4,%5,%6,%7}, {%8,%9}, {%0,%1,%2,%3};"
                 : "+f"(c[0]), "+f"(c[1]), "+f"(c[2]), "+f"(c[3])
                 : "r"(a[0]), "r"(a[1]), "r"(a[2]), "r"(a[3]), "r"(b0), "r"(b1));
}

// ---------------- fused prep: hist | split(x) | wtsplit1 | wtsplit2 ----------------
#define PREP_HIST_BLKS  1250
#define PREP_SPLIT_BLKS 20000   // N_NODES*F_IN / 256
#define PREP_WT1_BLKS   1024
#define PREP_WT2_BLKS   256
#define PREP_TOTAL (PREP_HIST_BLKS + PREP_SPLIT_BLKS + PREP_WT1_BLKS + PREP_WT2_BLKS)

__global__ void __launch_bounds__(256) prep_kernel(
    const int* __restrict__ dst, const float* __restrict__ x,
    const float* __restrict__ Wl1, const float* __restrict__ Wr1,
    const float* __restrict__ Wl2, const float* __restrict__ Wr2)
{
    int b = blockIdx.x;
    if (b < PREP_HIST_BLKS) {
        int e = b * 256 + threadIdx.x;
        if (e < N_EDGES) atomicAdd(&g_deg[dst[e]], 1);
    } else if (b < PREP_HIST_BLKS + PREP_SPLIT_BLKS) {
        int i = (b - PREP_HIST_BLKS) * 256 + threadIdx.x;
        float v = x[i];
        __nv_bfloat16 h = __float2bfloat16(v);
        g_xhi[i] = h;
        g_xlo[i] = __float2bfloat16(v - __bfloat162float(h));
    } else if (b < PREP_HIST_BLKS + PREP_SPLIT_BLKS + PREP_WT1_BLKS) {
        int i = (b - PREP_HIST_BLKS - PREP_SPLIT_BLKS) * 256 + threadIdx.x;
        int n = i >> 8, k = i & 255;
        float v = (n < 512) ? Wl1[(size_t)k * 512 + n] : Wr1[(size_t)k * 512 + (n - 512)];
        __nv_bfloat16 h = __float2bfloat16(v);
        g_wt1hi[i] = h;
        g_wt1lo[i] = __float2bfloat16(v - __bfloat162float(h));
    } else {
        int i = (b - PREP_HIST_BLKS - PREP_SPLIT_BLKS - PREP_WT1_BLKS) * 256 + threadIdx.x;
        int n = i >> 9, k = i & 511;
        float v = (n < 64) ? Wl2[(size_t)k * 64 + n] : Wr2[(size_t)k * 64 + (n - 64)];
        __nv_bfloat16 h = __float2bfloat16(v);
        g_wt2hi[i] = h;
        g_wt2lo[i] = __float2bfloat16(v - __bfloat162float(h));
    }
}

// ---------------- CSR scan + scatter ----------------
__global__ void scan_kernel() {
    __shared__ int sums[1024];
    const int CH = (N_NODES + 1023) / 1024;
    int t = threadIdx.x;
    int base = t * CH;
    int s = 0;
    for (int i = 0; i < CH; i++) {
        int idx = base + i;
        if (idx < N_NODES) s += g_deg[idx];
    }
    sums[t] = s;
    __syncthreads();
    for (int d = 1; d < 1024; d <<= 1) {
        int v = (t >= d) ? sums[t - d] : 0;
        __syncthreads();
        sums[t] += v;
        __syncthreads();
    }
    int pre = (t == 0) ? 0 : sums[t - 1];
    for (int i = 0; i < CH; i++) {
        int idx = base + i;
        if (idx < N_NODES) {
            g_off[idx] = pre;
            g_cur[idx] = pre;
            pre += g_deg[idx];
        }
    }
    if (t == 0) g_off[N_NODES] = sums[1023];
}

__global__ void scatter_kernel(const int* __restrict__ src, const int* __restrict__ dst) {
    int e = blockIdx.x * blockDim.x + threadIdx.x;
    if (e < N_EDGES) {
        int p = atomicAdd(&g_cur[dst[e]], 1);
        g_esrc[p] = src[e];
    }
}

// ---------------- mma.sync split-bf16 GEMM, cp.async double-buffered (round-12 shape) ----------------
#define BUF_AHI 0
#define BUF_ALO 16384
#define BUF_BHI 32768
#define BUF_BLO 40960
#define BUF_SZ  49152
#define SM_TOT  (2 * BUF_SZ)

__global__ void __launch_bounds__(256) gemm_mma_kernel(
    int M, int K, int ldc,
    const __nv_bfloat16* __restrict__ Ahi, const __nv_bfloat16* __restrict__ Alo,
    const __nv_bfloat16* __restrict__ Bhi, const __nv_bfloat16* __restrict__ Blo,
    float* __restrict__ C)
{
    extern __shared__ char smem[];
    uint32_t sb = smem_u32(smem);
    const int tid = threadIdx.x, wid = tid >> 5, lane = tid & 31;
    const int by = blockIdx.y, bx = blockIdx.x;
    const int warpM = wid & 3, warpN = wid >> 2;

    float acc[2][4][4];
#pragma unroll
    for (int a = 0; a < 2; a++)
#pragma unroll
        for (int b = 0; b < 4; b++)
#pragma unroll
            for (int c = 0; c < 4; c++) acc[a][b][c] = 0.f;

    const int nchunks = K >> 6;

    auto issue = [&](int ch) {
        uint32_t buf = sb + (uint32_t)(ch & 1) * BUF_SZ;
        int k0 = ch << 6;
#pragma unroll
        for (int it = 0; it < 4; it++) {
            int i = tid + 256 * it;
            int row = i >> 3, g = (i & 7) << 3;
            int gr = by * 128 + row;
            if (gr >= M) gr = M - 1;
            uint32_t so = SWZ128(row * 128 + g * 2);
            cp16(buf + BUF_AHI + so, Ahi + (size_t)gr * K + k0 + g);
            cp16(buf + BUF_ALO + so, Alo + (size_t)gr * K + k0 + g);
        }
#pragma unroll
        for (int it = 0; it < 2; it++) {
            int i = tid + 256 * it;
            int row = i >> 3, g = (i & 7) << 3;
            int gn = bx * 64 + row;
            uint32_t so = SWZ128(row * 128 + g * 2);
            cp16(buf + BUF_BHI + so, Bhi + (size_t)gn * K + k0 + g);
            cp16(buf + BUF_BLO + so, Blo + (size_t)gn * K + k0 + g);
        }
        cp_commit();
    };

    issue(0);
    for (int ch = 0; ch < nchunks; ch++) {
        if (ch + 1 < nchunks) {
            issue(ch + 1);
            cp_wait<1>();
        } else {
            cp_wait<0>();
        }
        __syncthreads();

        uint32_t buf = sb + (uint32_t)(ch & 1) * BUF_SZ;
#pragma unroll
        for (int ks = 0; ks < 4; ks++) {
            uint32_t ahi[2][4], alo[2][4], bhi[2][4], blo[2][4];
            int colb = ks * 32 + (lane >> 4) * 16;
#pragma unroll
            for (int mt = 0; mt < 2; mt++) {
                uint32_t off = SWZ128((warpM * 32 + mt * 16 + (lane & 15)) * 128 + colb);
                ldmx4(ahi[mt], buf + BUF_AHI + off);
                ldmx4(alo[mt], buf + BUF_ALO + off);
            }
#pragma unroll
            for (int nt = 0; nt < 2; nt++) {
                uint32_t off = SWZ128((warpN * 32 + nt * 16 + (lane & 15)) * 128 + colb);
                ldmx4(bhi[nt], buf + BUF_BHI + off);
                ldmx4(blo[nt], buf + BUF_BLO + off);
            }
#pragma unroll
            for (int mt = 0; mt < 2; mt++)
#pragma unroll
                for (int nt = 0; nt < 2; nt++)
#pragma unroll
                    for (int hf = 0; hf < 2; hf++) {
                        float* c = acc[mt][nt * 2 + hf];
                        mma16816(c, ahi[mt], bhi[nt][hf], bhi[nt][hf + 2]);
                        mma16816(c, ahi[mt], blo[nt][hf], blo[nt][hf + 2]);
                        mma16816(c, alo[mt], bhi[nt][hf], bhi[nt][hf + 2]);
                    }
        }
        __syncthreads();
    }

    float* stage = (float*)smem;
    {
        int r0 = lane >> 2, cb = (lane & 3) * 2;
#pragma unroll
        for (int mt = 0; mt < 2; mt++)
#pragma unroll
            for (int j = 0; j < 4; j++) {
                int col = warpN * 32 + (j >> 1) * 16 + (j & 1) * 8 + cb;
                float* st = stage + (warpM * 32 + mt * 16 + r0) * 64 + col;
                st[0]          = acc[mt][j][0];
                st[1]          = acc[mt][j][1];
                st[8 * 64]     = acc[mt][j][2];
                st[8 * 64 + 1] = acc[mt][j][3];
            }
    }
    __syncthreads();
    for (int i = tid; i < 2048; i += 256) {
        int row = i >> 4, c4 = (i & 15) << 2;
        int gr = by * 128 + row;
        if (gr < M)
            *(float4*)(C + (size_t)gr * ldc + bx * 64 + c4) = *(float4*)(stage + row * 64 + c4);
    }
}

// ---------------- layer 1: fused node kernel, 1 warp/head, lane-parallel indices ----------------
__global__ void __launch_bounds__(256) node1_fused_kernel(
    const float* __restrict__ att1, const float* __restrict__ b1)
{
    int n = blockIdx.x;
    int h = threadIdx.x >> 5, lane = threadIdx.x & 31;
    int beg = g_off[n], end = g_off[n + 1];
    int c0 = h * 64 + lane;

    float xr0 = g_xlr1[(size_t)n * 1024 + 512 + c0];
    float xr1 = g_xlr1[(size_t)n * 1024 + 512 + c0 + 32];
    float at0 = att1[c0], at1 = att1[c0 + 32];

    float m = -CUDART_INF_F, ssum = 0.f, acc0 = 0.f, acc1 = 0.f;

    for (int r = beg; r < end; r += 32) {
        int cnt = min(32, end - r);
        int sidx = (lane < cnt) ? g_esrc[r + lane] : 0;
        for (int j = 0; j < cnt; j += 8) {
            float xa[8], xb[8], sc[8];
#pragma unroll
            for (int k = 0; k < 8; k++) {
                int sn = __shfl_sync(0xffffffffu, sidx, j + k);
                const float* p = g_xlr1 + (size_t)sn * 1024 + h * 64;
                bool valid = (j + k) < cnt;
                xa[k] = valid ? p[lane] : 0.f;
                xb[k] = valid ? p[lane + 32] : 0.f;
            }
#pragma unroll
            for (int k = 0; k < 8; k++) {
                float u = xa[k] + xr0; u = u > 0.f ? u : NEG_SLOPE * u;
                float v = xb[k] + xr1; v = v > 0.f ? v : NEG_SLOPE * v;
                sc[k] = at0 * u + at1 * v;
            }
#pragma unroll
            for (int o = 16; o; o >>= 1)
#pragma unroll
                for (int k = 0; k < 8; k++)
                    sc[k] += __shfl_xor_sync(0xffffffffu, sc[k], o);
            float mn = m;
#pragma unroll
            for (int k = 0; k < 8; k++)
                if ((j + k) < cnt) mn = fmaxf(mn, sc[k]);
            float scale = __expf(m - mn);
            float wsum = 0.f, a0 = 0.f, a1 = 0.f;
#pragma unroll
            for (int k = 0; k < 8; k++) {
                float w = ((j + k) < cnt) ? __expf(sc[k] - mn) : 0.f;
                wsum += w;
                a0 += w * xa[k];
                a1 += w * xb[k];
            }
            ssum = ssum * scale + wsum;
            acc0 = acc0 * scale + a0;
            acc1 = acc1 * scale + a1;
            m = mn;
        }
    }

    float inv = 1.f / (ssum + SM_EPS);
    float v0 = acc0 * inv + b1[c0];
    float v1 = acc1 * inv + b1[c0 + 32];
    v0 = v0 > 0.f ? v0 : __expf(v0) - 1.f;
    v1 = v1 > 0.f ? v1 : __expf(v1) - 1.f;
    size_t o0 = (size_t)n * HC1 + c0, o1 = o0 + 32;
    __nv_bfloat16 h0 = __float2bfloat16(v0), h1 = __float2bfloat16(v1);
    g_hhi[o0] = h0; g_hlo[o0] = __float2bfloat16(v0 - __bfloat162float(h0));
    g_hhi[o1] = h1; g_hlo[o1] = __float2bfloat16(v1 - __bfloat162float(h1));
}

// ---------------- layer 2: fused node kernel, 1 warp/node; re-zeros g_deg for next run ----------------
__global__ void __launch_bounds__(256) node2_fused_kernel(
    const float* __restrict__ att2, const float* __restrict__ b2,
    float* __restrict__ out)
{
    // re-zero degree histogram for the next graph replay (g_deg unused below)
    {
        int gid = blockIdx.x * blockDim.x + threadIdx.x;
        if (gid < N_NODES) g_deg[gid] = 0;
    }

    int n = blockIdx.x * 8 + (threadIdx.x >> 5);
    if (n >= N_NODES) return;
    int lane = threadIdx.x & 31;
    int beg = g_off[n], end = g_off[n + 1];

    float xr0 = g_xlr2[(size_t)n * 128 + 64 + lane];
    float xr1 = g_xlr2[(size_t)n * 128 + 64 + lane + 32];
    float at0 = att2[lane], at1 = att2[lane + 32];

    float m = -CUDART_INF_F, ssum = 0.f, acc0 = 0.f, acc1 = 0.f;

    for (int r = beg; r < end; r += 32) {
        int cnt = min(32, end - r);
        int sidx = (lane < cnt) ? g_esrc[r + lane] : 0;
        for (int j = 0; j < cnt; j += 8) {
            float xa[8], xb[8], sc[8];
#pragma unroll
            for (int k = 0; k < 8; k++) {
                int sn = __shfl_sync(0xffffffffu, sidx, j + k);
                const float* p = g_xlr2 + (size_t)sn * 128;
                bool valid = (j + k) < cnt;
                xa[k] = valid ? p[lane] : 0.f;
                xb[k] = valid ? p[lane + 32] : 0.f;
            }
#pragma unroll
            for (int k = 0; k < 8; k++) {
                float u = xa[k] + xr0; u = u > 0.f ? u : NEG_SLOPE * u;
                float v = xb[k] + xr1; v = v > 0.f ? v : NEG_SLOPE * v;
                sc[k] = at0 * u + at1 * v;
            }
#pragma unroll
            for (int o = 16; o; o >>= 1)
#pragma unroll
                for (int k = 0; k < 8; k++)
                    sc[k] += __shfl_xor_sync(0xffffffffu, sc[k], o);
            float mn = m;
#pragma unroll
            for (int k = 0; k < 8; k++)
                if ((j + k) < cnt) mn = fmaxf(mn, sc[k]);
            float scale = __expf(m - mn);
            float wsum = 0.f, a0 = 0.f, a1 = 0.f;
#pragma unroll
            for (int k = 0; k < 8; k++) {
                float w = ((j + k) < cnt) ? __expf(sc[k] - mn) : 0.f;
                wsum += w;
                a0 += w * xa[k];
                a1 += w * xb[k];
            }
            ssum = ssum * scale + wsum;
            acc0 = acc0 * scale + a0;
            acc1 = acc1 * scale + a1;
            m = mn;
        }
    }

    float inv = 1.f / (ssum + SM_EPS);
    out[(size_t)n * NCLS + lane]      = acc0 * inv + b2[lane];
    out[(size_t)n * NCLS + lane + 32] = acc1 * inv + b2[lane + 32];
}

// ---------------- launch ----------------
extern "C" void kernel_launch(void* const* d_in, const int* in_sizes, int n_in,
                              void* d_out, int out_size)
{
    (void)in_sizes; (void)n_in; (void)out_size;
    const float* x    = (const float*)d_in[0];
    const int*   ei   = (const int*)d_in[1];
    const int*   src  = ei;
    const int*   dst  = ei + N_EDGES;
    const float* Wl1  = (const float*)d_in[2];
    const float* Wr1  = (const float*)d_in[3];
    const float* att1 = (const float*)d_in[4];
    const float* b1   = (const float*)d_in[5];
    const float* Wl2  = (const float*)d_in[6];
    const float* Wr2  = (const float*)d_in[7];
    const float* att2 = (const float*)d_in[8];
    const float* b2   = (const float*)d_in[9];
    float* out = (float*)d_out;

    cudaFuncSetAttribute(gemm_mma_kernel, cudaFuncAttributeMaxDynamicSharedMemorySize, SM_TOT);

    void *p_xlr1, *p_xlr2;
    void *p_xhi, *p_xlo, *p_hhi, *p_hlo, *p_w1h, *p_w1l, *p_w2h, *p_w2l;
    cudaGetSymbolAddress(&p_xlr1, g_xlr1);
    cudaGetSymbolAddress(&p_xlr2, g_xlr2);
    cudaGetSymbolAddress(&p_xhi, g_xhi);
    cudaGetSymbolAddress(&p_xlo, g_xlo);
    cudaGetSymbolAddress(&p_hhi, g_hhi);
    cudaGetSymbolAddress(&p_hlo, g_hlo);
    cudaGetSymbolAddress(&p_w1h, g_wt1hi);
    cudaGetSymbolAddress(&p_w1l, g_wt1lo);
    cudaGetSymbolAddress(&p_w2h, g_wt2hi);
    cudaGetSymbolAddress(&p_w2l, g_wt2lo);

    // g_deg is zero at entry (static init on first run; node2 re-zeros it each run).
    // (1) fused prep: hist | x-split | wt1 transpose-split | wt2 transpose-split
    prep_kernel<<<PREP_TOTAL, 256>>>(dst, x, Wl1, Wr1, Wl2, Wr2);
    // (2) CSR scan, (3) scatter
    scan_kernel<<<1, 1024>>>();
    scatter_kernel<<<(N_EDGES + 255) / 256, 256>>>(src, dst);

    // (4) layer-1 projections: g_xlr1 [N,1024]
    {
        dim3 grid(1024 / 64, (N_NODES + 127) / 128);
        gemm_mma_kernel<<<grid, 256, SM_TOT>>>(
            N_NODES, 256, 1024,
            (const __nv_bfloat16*)p_xhi, (const __nv_bfloat16*)p_xlo,
            (const __nv_bfloat16*)p_w1h, (const __nv_bfloat16*)p_w1l,
            (float*)p_xlr1);
    }
    // (5) layer-1 node phase   <-- profiled slot (5th launch)
    node1_fused_kernel<<<N_NODES, 256>>>(att1, b1);

    // (6) layer-2 projections: g_xlr2 [N,128]
    {
        dim3 grid(128 / 64, (N_NODES + 127) / 128);
        gemm_mma_kernel<<<grid, 256, SM_TOT>>>(
            N_NODES, 512, 128,
            (const __nv_bfloat16*)p_hhi, (const __nv_bfloat16*)p_hlo,
            (const __nv_bfloat16*)p_w2h, (const __nv_bfloat16*)p_w2l,
            (float*)p_xlr2);
    }
    // (7) layer-2 node phase -> output (+ re-zero g_deg)
    node2_fused_kernel<<<(N_NODES + 7) / 8, 256>>>(att2, b2, out);
}